// round 16
// baseline (speedup 1.0000x reference)
#include <cuda_runtime.h>
#include <math.h>

#define B_SZ   64
#define IN_SZ  1024
#define OUT_SZ 512
#define T_SZ   512
#define TAU_F  16.0f
#define V_TH   1.0f
#define WIN    8
#define NWE    32          // entry windows (spikes < 256 -> k <= 256)
#define NW     64          // total windows
#define ESTRIDE 1056
#define CHW    8           // prefetch depth in delta kernel
#define SENT_MAX 256
#define DFACT  0.60653065971263342f   // exp(-WIN/TAU) = exp(-0.5)
#define TH1    6.26569003f            // 16*exp(1/16 - 1)  (= V_TH/dec at dt=1)
#define THR    1.06449445891786f      // exp(1/16)
#define TWIN   4                      // windows per resolve tile
#define TROWS  (TWIN * WIN)           // 32 rows per tile
#define NTILE  (NWE / TWIN)           // 8 tiles

// Scratch (no dynamic allocation allowed)
__device__ float4 g_entries[B_SZ * ESTRIDE];        // {k, idx, u, p} sorted per batch
__device__ float  g_wT[IN_SZ * OUT_SZ];             // transposed weights [IN][OUT]
__device__ int    g_wstart[B_SZ * (NWE + 1)];       // per-batch window entry offsets
__device__ float2 g_P[B_SZ * NWE * OUT_SZ];         // per-window partials {PA, PB}
__device__ float  g_C[B_SZ * NWE * WIN * OUT_SZ];   // c1(dt) checkpoints (33.5 MB)

// ---------------------------------------------------------------------------
// Prep: blocks [0,64) bucket-sort spikes per batch (warp-shuffle scan) +
// window offsets; blocks [64,192) float4 tiled transpose.
// ---------------------------------------------------------------------------
__global__ void __launch_bounds__(1024) prep_kernel(const float* __restrict__ in_spike,
                                                    const float* __restrict__ w) {
    __shared__ int   hist[512];
    __shared__ int   scanv[512];
    __shared__ int   offs[512];
    __shared__ int   wsum[16];
    __shared__ float tile[64][65];

    const int bid = blockIdx.x;
    const int i   = threadIdx.x;

    if (bid < B_SZ) {
        const int b = bid;
        if (i < 512) hist[i] = 0;
        __syncthreads();

        const float s = in_spike[b * IN_SZ + i];
        int k = (int)floorf(s) + 1;
        k = max(1, min(k, NWE * WIN));           // k in [1, 256]
        atomicAdd(&hist[k], 1);
        __syncthreads();

        int h0 = 0, incl = 0;
        if (i < 512) {
            h0 = hist[i]; incl = h0;
            #pragma unroll
            for (int d = 1; d < 32; d <<= 1) {
                int n = __shfl_up_sync(0xffffffffu, incl, d);
                if ((i & 31) >= d) incl += n;
            }
            if ((i & 31) == 31) wsum[i >> 5] = incl;
        }
        __syncthreads();
        if (i < 16) {
            int s2 = wsum[i];
            #pragma unroll
            for (int d = 1; d < 16; d <<= 1) {
                int n = __shfl_up_sync(0x0000ffffu, s2, d);
                if (i >= d) s2 += n;
            }
            wsum[i] = s2;
        }
        __syncthreads();
        if (i < 512) {
            const int wrp = i >> 5;
            if (wrp > 0) incl += wsum[wrp - 1];
            scanv[i] = incl;          // inclusive
            offs[i]  = incl - h0;     // exclusive
        }
        __syncthreads();
        if (i <= NWE) g_wstart[b * (NWE + 1) + i] = (i == 0) ? 0 : scanv[i * WIN];

        const int pos = atomicAdd(&offs[k], 1);
        const int t0k = (k - 1) & ~(WIN - 1);
        const float rel = s - (float)t0k;              // [0, WIN)
        const float u = expf(rel * (1.0f / TAU_F));
        const float p = rel * u;
        g_entries[b * ESTRIDE + pos] = make_float4((float)k, (float)i, u, p);
    } else {
        // transpose 64x64 tile: w[OUT][IN] -> g_wT[IN][OUT]
        const int tb = bid - B_SZ;                 // 0..127
        const int i0 = (tb & 15) * 64;             // IN tile
        const int o0 = (tb >> 4) * 64;             // OUT tile
        const int tx = i & 15, ty = i >> 4;        // 16 x 64
        const float4 v = *(const float4*)&w[(o0 + ty) * IN_SZ + i0 + 4 * tx];
        tile[4 * tx + 0][ty] = v.x;
        tile[4 * tx + 1][ty] = v.y;
        tile[4 * tx + 2][ty] = v.z;
        tile[4 * tx + 3][ty] = v.w;
        __syncthreads();
        float4 r;
        r.x = tile[ty][4 * tx + 0];
        r.y = tile[ty][4 * tx + 1];
        r.z = tile[ty][4 * tx + 2];
        r.w = tile[ty][4 * tx + 3];
        *(float4*)&g_wT[(i0 + ty) * OUT_SZ + o0 + 4 * tx] = r;
    }
}

// ---------------------------------------------------------------------------
// Delta kernel (single entry x weight gather pass). Per (b, W, o):
// checkpoints c1(dt) = dt*dA(dt) - dB(dt) (SMEM staged, coalesced dump) and
// window partials (PA,PB). 4 outputs/thread, grid (NWE, B), CHW=8 prefetch.
// ---------------------------------------------------------------------------
__global__ void __launch_bounds__(128) delta_kernel() {
    __shared__ float4 sent[SENT_MAX];          // 4 KB
    __shared__ float4 schk[WIN][128];          // 16 KB checkpoint staging
    const int W = blockIdx.x, b = blockIdx.y;
    const int tid = threadIdx.x;
    const int o = 4 * tid;

    const int start = g_wstart[b * (NWE + 1) + W];
    const int count = g_wstart[b * (NWE + 1) + W + 1] - start;
    const float kbase = (float)(W * WIN);

    float A0 = 0.f, B0 = 0.f, A1 = 0.f, B1 = 0.f;
    float A2 = 0.f, B2 = 0.f, A3 = 0.f, B3 = 0.f;

    const float4* __restrict__ ge = g_entries + b * ESTRIDE + start;
    const float4* __restrict__ wp = (const float4*)g_wT + tid;

    int t_dt = 1;
    for (int base = 0; base < count; base += SENT_MAX) {
        const int tcount = min(count - base, SENT_MAX);
        const int padded = (tcount + CHW - 1) & ~(CHW - 1);
        for (int j = tid; j < padded; j += 128) {
            float4 e = (j < tcount) ? ge[base + j] : make_float4(1e9f, 0.f, 0.f, 0.f);
            e.x -= kbase;                       // window-relative arrival (1..WIN)
            sent[j] = e;
        }
        __syncthreads();

        float4 wc[CHW];
        #pragma unroll
        for (int q = 0; q < CHW; q++) wc[q] = wp[((int)sent[q].y) << 7];
        const int nch = padded / CHW;
        for (int c = 0; c < nch; c++) {
            float4 wn[CHW];
            if (c + 1 < nch) {
                #pragma unroll
                for (int q = 0; q < CHW; q++)
                    wn[q] = wp[((int)sent[(c + 1) * CHW + q].y) << 7];
            }
            #pragma unroll
            for (int q = 0; q < CHW; q++) {
                const float4 e = sent[c * CHW + q];
                while ((float)t_dt < e.x && t_dt <= WIN) {   // uniform across block
                    const float tf = (float)t_dt;
                    float4 cv;
                    cv.x = fmaf(tf, A0, -B0);
                    cv.y = fmaf(tf, A1, -B1);
                    cv.z = fmaf(tf, A2, -B2);
                    cv.w = fmaf(tf, A3, -B3);
                    schk[t_dt - 1][tid] = cv;                // STS, no scoreboard
                    t_dt++;
                }
                A0 = fmaf(wc[q].x, e.z, A0); B0 = fmaf(wc[q].x, e.w, B0);
                A1 = fmaf(wc[q].y, e.z, A1); B1 = fmaf(wc[q].y, e.w, B1);
                A2 = fmaf(wc[q].z, e.z, A2); B2 = fmaf(wc[q].z, e.w, B2);
                A3 = fmaf(wc[q].w, e.z, A3); B3 = fmaf(wc[q].w, e.w, B3);
            }
            #pragma unroll
            for (int q = 0; q < CHW; q++) wc[q] = wn[q];
        }
        __syncthreads();
    }
    while (t_dt <= WIN) {                                    // tail checkpoints
        const float tf = (float)t_dt;
        float4 cv;
        cv.x = fmaf(tf, A0, -B0);
        cv.y = fmaf(tf, A1, -B1);
        cv.z = fmaf(tf, A2, -B2);
        cv.w = fmaf(tf, A3, -B3);
        schk[t_dt - 1][tid] = cv;
        t_dt++;
    }

    // coalesced dump: 8 rows of 128 float4
    float* __restrict__ cp = g_C + ((b * NWE + W) * WIN) * OUT_SZ + o;
    #pragma unroll
    for (int dt = 0; dt < WIN; dt++)
        *(float4*)(cp + dt * OUT_SZ) = schk[dt][tid];

    float2* Pp = &g_P[(b * NWE + W) * OUT_SZ + o];
    *(float4*)(Pp)     = make_float4(A0, B0, A1, B1);
    *(float4*)(Pp + 2) = make_float4(A2, B2, A3, B3);
}

// ---------------------------------------------------------------------------
// Resolve kernel (fused scan + test): grid (OUT/128, B), thread = one (b,o)
// column for all 64 windows. g_C streamed through double-buffered SMEM tiles
// (4 windows = 32 rows x 128 floats per tile); window recurrence in registers;
// direct output write (single writer, no atomics).
// ---------------------------------------------------------------------------
__global__ void __launch_bounds__(128) resolve_kernel(float* __restrict__ out) {
    __shared__ float sc[2][TROWS * 128];    // 2 x 16 KB
    const int b   = blockIdx.y;
    const int o0  = blockIdx.x * 128;
    const int tid = threadIdx.x;

    float th[WIN];
    th[0] = TH1;
    #pragma unroll
    for (int j = 1; j < WIN; j++) th[j] = th[j - 1] * THR;

    // preload all window partials for this column (MLP = 32)
    float2 P[NWE];
    #pragma unroll
    for (int w = 0; w < NWE; w++)
        P[w] = g_P[(b * NWE + w) * OUT_SZ + o0 + tid];

    // tile loader: rows [tile*TROWS, tile*TROWS+TROWS) of the (b, o-slice)
    const float4* __restrict__ csrc =
        (const float4*)(g_C + ((size_t)b * NWE * WIN) * OUT_SZ + o0);

    // preload tile 0
    {
        const float4* src = csrc;           // row stride = OUT_SZ/4 = 128 float4
        float4* dst = (float4*)sc[0];
        #pragma unroll
        for (int it = 0; it < TROWS * 32 / 128; it++) {     // 8 iters
            const int j = tid + it * 128;
            const int r = j >> 5, cc = j & 31;
            dst[r * 32 + cc] = src[r * 128 + cc];
        }
    }
    __syncthreads();

    int res = 1 << 30;
    float As = 0.f, Bs = 0.f;

    for (int tile = 0; tile < NTILE; tile++) {
        const int buf = tile & 1;
        if (tile + 1 < NTILE) {             // issue next tile's loads (other buf)
            const float4* src = csrc + (size_t)(tile + 1) * TROWS * 128;
            float4* dst = (float4*)sc[buf ^ 1];
            #pragma unroll
            for (int it = 0; it < TROWS * 32 / 128; it++) {
                const int j = tid + it * 128;
                const int r = j >> 5, cc = j & 31;
                dst[r * 32 + cc] = src[r * 128 + cc];
            }
        }
        const float* __restrict__ cb = sc[buf];
        #pragma unroll
        for (int Wl = 0; Wl < TWIN; Wl++) {
            const int W = tile * TWIN + Wl;
            int c = 1000;
            #pragma unroll
            for (int dt = WIN; dt >= 1; dt--) {
                const float cv = cb[(Wl * WIN + dt - 1) * 128 + tid];
                if (fmaf((float)dt, As, -Bs) + cv >= th[dt - 1]) c = dt;
            }
            if (res == (1 << 30) && c <= WIN) res = W * WIN + c;
            As = DFACT * (As + P[W].x);
            Bs = DFACT * (Bs + P[W].y) - (float)WIN * As;
        }
        __syncthreads();
    }

    // entry-free tail windows (c1 = 0)
    if (res == (1 << 30)) {
        for (int W = NWE; W < NW; W++) {
            int c = 1000;
            #pragma unroll
            for (int dt = WIN; dt >= 1; dt--)
                if (fmaf((float)dt, As, -Bs) >= th[dt - 1]) c = dt;
            if (c <= WIN) { res = W * WIN + c; break; }
            As = DFACT * As;
            Bs = DFACT * Bs - (float)WIN * As;
        }
    }
    out[b * OUT_SZ + o0 + tid] = (res == (1 << 30)) ? 512.0f : (float)res;
}

// ---------------------------------------------------------------------------
extern "C" void kernel_launch(void* const* d_in, const int* in_sizes, int n_in,
                              void* d_out, int out_size) {
    const float* in_spike = (const float*)d_in[0];  // [B, IN]
    const float* weight   = (const float*)d_in[1];  // [OUT, IN]
    float* out = (float*)d_out;                     // [B, OUT]
    (void)in_sizes; (void)n_in; (void)out_size;

    prep_kernel<<<B_SZ + 128, 1024>>>(in_spike, weight);
    delta_kernel<<<dim3(NWE, B_SZ), 128>>>();
    resolve_kernel<<<dim3(OUT_SZ / 128, B_SZ), 128>>>(out);
}